// round 12
// baseline (speedup 1.0000x reference)
#include <cuda_runtime.h>
#include <cuda_fp8.h>
#include <cstdint>
#include <math.h>

// NT-Xent loss, B=4096, D=128, N=8192, T=0.5 — mma.sync FP8 (e4m3, m16n8k32)
// R12: fp8 doubles legacy-mma tensor throughput vs bf16; rows shrink to 128B;
// interleaved MUFU epilogue retained; finish = one warp per positive pair.

#define NB   4096
#define NN   8192
#define C1   2.8853900817779268f   // 2*log2(e)

__device__ __align__(16) unsigned char g_Zb[NN * 128];  // e4m3 rows, 128B each
__device__ float g_rowsum[NN];
__device__ float g_self[NN];
__device__ float g_loss;
__device__ unsigned int g_done;

// ---------- helpers ----------
static __device__ __forceinline__ uint32_t smem_u32(const void* p) {
    uint32_t a;
    asm("{ .reg .u64 t; cvta.to.shared.u64 t, %1; cvt.u32.u64 %0, t; }"
        : "=r"(a) : "l"(p));
    return a;
}
#define CP_ASYNC16(dst, src) \
    asm volatile("cp.async.cg.shared.global [%0], [%1], 16;" :: "r"(dst), "l"(src))
#define CP_COMMIT() asm volatile("cp.async.commit_group;")
#define CP_WAIT(n)  asm volatile("cp.async.wait_group %0;" :: "n"(n))

static __device__ __forceinline__ void ldm_x4(uint32_t& r0, uint32_t& r1,
                                              uint32_t& r2, uint32_t& r3,
                                              uint32_t addr) {
    asm volatile("ldmatrix.sync.aligned.m8n8.x4.shared.b16 {%0,%1,%2,%3}, [%4];"
                 : "=r"(r0), "=r"(r1), "=r"(r2), "=r"(r3) : "r"(addr));
}
static __device__ __forceinline__ void mma_fp8(float* c, const uint32_t* a,
                                               const uint32_t* b) {
    asm volatile(
        "mma.sync.aligned.m16n8k32.row.col.f32.e4m3.e4m3.f32 "
        "{%0,%1,%2,%3}, {%4,%5,%6,%7}, {%8,%9}, {%0,%1,%2,%3};"
        : "+f"(c[0]), "+f"(c[1]), "+f"(c[2]), "+f"(c[3])
        : "r"(a[0]), "r"(a[1]), "r"(a[2]), "r"(a[3]), "r"(b[0]), "r"(b[1]));
}
static __device__ __forceinline__ float ex2f(float x) {
    float r;
    asm("ex2.approx.f32 %0, %1;" : "=f"(r) : "f"(x));
    return r;
}
static __device__ __forceinline__ float fp8_to_f(uint32_t u, int b) {
    __nv_fp8_e4m3 v;
    v.__x = (__nv_fp8_storage_t)((u >> (8 * b)) & 0xffu);
    return (float)v;
}

// One 32-col half-step: fill acc[32] (MMA, K=128 in 4 k32 steps) while
// draining epi[32] of the PREVIOUS half (8 ex2 per k-step).
static __device__ __forceinline__ void half_step(
    float* __restrict__ acc, float* __restrict__ epi, float* __restrict__ rowacc,
    uint32_t buf, int ncol0, int n_loc, int cpar, const uint32_t (*Ar)[4][4])
{
    #pragma unroll
    for (int f = 0; f < 32; f++) acc[f] = 0.f;
    #pragma unroll
    for (int ks = 0; ks < 4; ks++) {
        uint32_t bfr[8];
        #pragma unroll
        for (int pr = 0; pr < 2; pr++) {
            int n = ncol0 + pr * 16 + n_loc;
            uint32_t addr = buf + (uint32_t)n * 128u
                          + (uint32_t)(((2 * ks + cpar) ^ (n_loc & 7)) * 16);
            ldm_x4(bfr[pr*4+0], bfr[pr*4+1], bfr[pr*4+2], bfr[pr*4+3], addr);
        }
        #pragma unroll
        for (int mi = 0; mi < 2; mi++) {
            mma_fp8(&acc[mi*16 + 0],  Ar[mi][ks], &bfr[0]);
            mma_fp8(&acc[mi*16 + 4],  Ar[mi][ks], &bfr[2]);
            mma_fp8(&acc[mi*16 + 8],  Ar[mi][ks], &bfr[4]);
            mma_fp8(&acc[mi*16 + 12], Ar[mi][ks], &bfr[6]);
        }
        #pragma unroll
        for (int u = 0; u < 8; u++) {
            int f = ks * 8 + u;
            rowacc[((f >> 4) << 1) | ((f & 3) >> 1)]
                += ex2f(fmaf(epi[f], C1, -C1));
        }
    }
}

// ---------- kernels ----------
__global__ void norm_kernel(const float* __restrict__ zi,
                            const float* __restrict__ zj) {
    int gt = blockIdx.x * blockDim.x + threadIdx.x;
    if (gt < NN) g_rowsum[gt] = 0.f;
    if (gt == 0) { g_loss = 0.f; g_done = 0u; }
    int row = gt >> 5;
    int lane = threadIdx.x & 31;
    if (row >= NN) return;
    const float* src = (row < NB) ? (zi + (size_t)row * 128)
                                  : (zj + (size_t)(row - NB) * 128);
    float4 v = ((const float4*)src)[lane];
    float ss = v.x*v.x + v.y*v.y + v.z*v.z + v.w*v.w;
    #pragma unroll
    for (int o = 16; o; o >>= 1) ss += __shfl_xor_sync(0xffffffffu, ss, o);
    float inv = 1.0f / fmaxf(sqrtf(ss), 1e-12f);

    __nv_fp8_e4m3 q0(v.x * inv), q1(v.y * inv), q2(v.z * inv), q3(v.w * inv);
    float f0 = (float)q0, f1 = (float)q1, f2 = (float)q2, f3 = (float)q3;
    float sd = f0*f0 + f1*f1 + f2*f2 + f3*f3;      // fp8-exact self-dot
    #pragma unroll
    for (int o = 16; o; o >>= 1) sd += __shfl_xor_sync(0xffffffffu, sd, o);
    if (lane == 0) g_self[row] = sd;

    uint32_t pk = (uint32_t)q0.__x | ((uint32_t)q1.__x << 8)
                | ((uint32_t)q2.__x << 16) | ((uint32_t)q3.__x << 24);
    *reinterpret_cast<uint32_t*>(g_Zb + (size_t)row * 128 + lane * 4) = pk;
}

// 128 blocks = 64 row-panels(128 rows) x 2 col-halves(4096 cols); one wave.
__global__ void __launch_bounds__(256, 1) sim_kernel() {
    extern __shared__ unsigned char smraw[];
    uint32_t s0 = smem_u32(smraw);
    uint32_t Bb[2] = { s0, s0 + 16384u };
    uint32_t Ab = s0 + 32768u;                    // 16KB A stage

    int tid = threadIdx.x, lane = tid & 31, w = tid >> 5;
    int wm = w & 3, wn = w >> 2;
    int rp = blockIdx.x >> 1, half = blockIdx.x & 1;
    int r0 = rp * 128;
    const unsigned char* Z = g_Zb;

    #pragma unroll
    for (int i = 0; i < 4; i++) {                 // stage A: 128 rows x 128B
        int idx = tid + i * 256;                  // 1024 chunks
        int row = idx >> 3, c = idx & 7;
        uint32_t dst = Ab + row * 128 + ((c ^ (row & 7)) * 16);
        CP_ASYNC16(dst, Z + (size_t)(r0 + row) * 128 + c * 16);
    }
    CP_COMMIT();

    #pragma unroll
    for (int t = 0; t < 2; t++) {                 // prefetch B tiles 0,1 (16KB)
        int cg0 = half * 4096 + t * 128;
        #pragma unroll
        for (int i = 0; i < 4; i++) {
            int idx = tid + i * 256;
            int n = idx >> 3, c = idx & 7;
            uint32_t dst = Bb[t] + n * 128 + ((c ^ (n & 7)) * 16);
            CP_ASYNC16(dst, Z + (size_t)(cg0 + n) * 128 + c * 16);
        }
        CP_COMMIT();
    }

    CP_WAIT(2);
    __syncthreads();
    uint32_t Ar[2][4][4];                         // 2 m-atoms x 4 k32-steps
    {
        int row_loc = (lane & 7) + ((lane >> 3) & 1) * 8;
        int kpar = (lane >> 4) & 1;
        uint32_t abase = Ab + (uint32_t)(wm * 32 + row_loc) * 128u;
        #pragma unroll
        for (int ma = 0; ma < 2; ma++)
            #pragma unroll
            for (int ks = 0; ks < 4; ks++) {
                uint32_t addr = abase + (uint32_t)(ma * 16) * 128u
                              + (uint32_t)(((2 * ks + kpar) ^ (row_loc & 7)) * 16);
                ldm_x4(Ar[ma][ks][0], Ar[ma][ks][1], Ar[ma][ks][2], Ar[ma][ks][3], addr);
            }
    }

    int n_loc = (lane & 7) + ((lane >> 4) << 3);
    int cpar = (lane >> 3) & 1;

    float rowacc[4] = {0.f, 0.f, 0.f, 0.f};
    float accA[32], accB[32];
    #pragma unroll
    for (int f = 0; f < 32; f++) accB[f] = -__int_as_float(0x7f800000);  // -inf

    for (int t = 0; t < 32; t++) {
        uint32_t buf = Bb[t & 1];
        CP_WAIT(1);
        __syncthreads();

        int nbase = wn * 64;
        half_step(accA, accB, rowacc, buf, nbase,      n_loc, cpar, Ar);
        half_step(accB, accA, rowacc, buf, nbase + 32, n_loc, cpar, Ar);

        __syncthreads();                          // all warps done reading buf
        if (t + 2 < 32) {
            int cg0 = half * 4096 + (t + 2) * 128;
            #pragma unroll
            for (int i = 0; i < 4; i++) {
                int idx = tid + i * 256;
                int n = idx >> 3, c = idx & 7;
                uint32_t dst = buf + n * 128 + ((c ^ (n & 7)) * 16);
                CP_ASYNC16(dst, Z + (size_t)(cg0 + n) * 128 + c * 16);
            }
        }
        CP_COMMIT();
    }

    // flush final half
    #pragma unroll
    for (int f = 0; f < 32; f++)
        rowacc[((f >> 4) << 1) | ((f & 3) >> 1)] += ex2f(fmaf(accB[f], C1, -C1));

    #pragma unroll
    for (int k = 0; k < 4; k++) {
        rowacc[k] += __shfl_xor_sync(0xffffffffu, rowacc[k], 1);
        rowacc[k] += __shfl_xor_sync(0xffffffffu, rowacc[k], 2);
    }
    if ((lane & 3) == 0) {
        int rbase = r0 + wm * 32 + (lane >> 2);
        atomicAdd(&g_rowsum[rbase],      rowacc[0]);
        atomicAdd(&g_rowsum[rbase + 8],  rowacc[1]);
        atomicAdd(&g_rowsum[rbase + 16], rowacc[2]);
        atomicAdd(&g_rowsum[rbase + 24], rowacc[3]);
    }
}

// one warp per POSITIVE PAIR (p, p+NB): pos dot once, both rows' losses.
__global__ void finish_kernel(float* __restrict__ out) {
    __shared__ float sh[8];
    int tid = threadIdx.x, lane = tid & 31, w = tid >> 5;
    int p = blockIdx.x * 8 + w;                   // 0..4095
    int q = p + NB;
    uint32_t ua = *reinterpret_cast<const uint32_t*>(g_Zb + (size_t)p * 128 + lane * 4);
    uint32_t ub = *reinterpret_cast<const uint32_t*>(g_Zb + (size_t)q * 128 + lane * 4);
    float pd = 0.f;
    #pragma unroll
    for (int b = 0; b < 4; b++)
        pd += fp8_to_f(ua, b) * fp8_to_f(ub, b);
    #pragma unroll
    for (int o = 16; o; o >>= 1) pd += __shfl_xor_sync(0xffffffffu, pd, o);
    if (lane == 0) {
        float self_p = ex2f(fmaf(g_self[p], C1, -C1));
        float self_q = ex2f(fmaf(g_self[q], C1, -C1));
        float pos = 2.0f * pd;                    // s(p,q) = s(q,p)
        sh[w] = 4.0f + logf(g_rowsum[p] - self_p) + logf(g_rowsum[q] - self_q)
              - 2.0f * pos;
    }
    __syncthreads();
    if (tid == 0) {
        float t = 0.f;
        #pragma unroll
        for (int k = 0; k < 8; k++) t += sh[k];
        atomicAdd(&g_loss, t);
        __threadfence();
        unsigned int done = atomicAdd(&g_done, 1u);
        if (done == (unsigned int)(gridDim.x - 1)) {
            out[0] = g_loss * (1.0f / (float)NN);
        }
    }
}

extern "C" void kernel_launch(void* const* d_in, const int* in_sizes, int n_in,
                              void* d_out, int out_size) {
    const float* zi = (const float*)d_in[0];
    const float* zj = (const float*)d_in[1];
    float* out = (float*)d_out;
    (void)in_sizes; (void)n_in; (void)out_size;

    (void)cudaFuncSetAttribute(sim_kernel,
                               cudaFuncAttributeMaxDynamicSharedMemorySize,
                               49152);

    norm_kernel<<<1024, 256>>>(zi, zj);
    sim_kernel<<<128, 256, 49152>>>();
    finish_kernel<<<NB / 8, 256>>>(out);
}

// round 13
// speedup vs baseline: 1.2645x; 1.2645x over previous
#include <cuda_runtime.h>
#include <cuda_bf16.h>
#include <cstdint>
#include <math.h>

// NT-Xent loss, B=4096, D=128, N=8192, T=0.5 — mma.sync bf16, SYMMETRIC
// R13: compute only the 2080 upper-triangular 128x128 panel-pairs; each tile
// feeds rowsum (row-side) and, for off-diagonal tiles, colsum -> rowsum of the
// column panel (symmetry). Halves tensor AND MUFU work. Flat tile queue over
// a 148-block grid, A+B double-buffered cp.async.

#define NB   4096
#define NN   8192
#define NT   2080            // 64*65/2 panel-pairs
#define GRID 148
#define C1   2.8853900817779268f   // 2*log2(e)

__device__ __align__(16) unsigned char g_Zb[NN * 256];  // bf16 rows, 256B each
__device__ float g_rowsum[NN];
__device__ float g_self[NN];
__device__ float g_loss;
__device__ unsigned int g_done;

// ---------- helpers ----------
static __device__ __forceinline__ uint32_t smem_u32(const void* p) {
    uint32_t a;
    asm("{ .reg .u64 t; cvta.to.shared.u64 t, %1; cvt.u32.u64 %0, t; }"
        : "=r"(a) : "l"(p));
    return a;
}
#define CP_ASYNC16(dst, src) \
    asm volatile("cp.async.cg.shared.global [%0], [%1], 16;" :: "r"(dst), "l"(src))
#define CP_COMMIT() asm volatile("cp.async.commit_group;")
#define CP_WAIT(n)  asm volatile("cp.async.wait_group %0;" :: "n"(n))

static __device__ __forceinline__ void ldm_x4(uint32_t& r0, uint32_t& r1,
                                              uint32_t& r2, uint32_t& r3,
                                              uint32_t addr) {
    asm volatile("ldmatrix.sync.aligned.m8n8.x4.shared.b16 {%0,%1,%2,%3}, [%4];"
                 : "=r"(r0), "=r"(r1), "=r"(r2), "=r"(r3) : "r"(addr));
}
static __device__ __forceinline__ void mma16816(float* c, const uint32_t* a,
                                                const uint32_t* b) {
    asm volatile(
        "mma.sync.aligned.m16n8k16.row.col.f32.bf16.bf16.f32 "
        "{%0,%1,%2,%3}, {%4,%5,%6,%7}, {%8,%9}, {%0,%1,%2,%3};"
        : "+f"(c[0]), "+f"(c[1]), "+f"(c[2]), "+f"(c[3])
        : "r"(a[0]), "r"(a[1]), "r"(a[2]), "r"(a[3]), "r"(b[0]), "r"(b[1]));
}
static __device__ __forceinline__ float ex2f(float x) {
    float r;
    asm("ex2.approx.f32 %0, %1;" : "=f"(r) : "f"(x));
    return r;
}

// tile index -> (row panel, col panel), upper triangle incl. diagonal
static __device__ __forceinline__ void decode(int k, int& r, int& c) {
    int rem = k, rr = 0;
    while (rem >= 64 - rr) { rem -= 64 - rr; rr++; }
    r = rr; c = rr + rem;
}

// stage both panels (r rows -> Abuf, c rows -> Bbuf); 16 cp.async per thread
static __device__ __forceinline__ void stage(uint32_t Abuf, uint32_t Bbuf,
                                             int r, int c, int tid) {
    const unsigned char* Z = g_Zb;
    #pragma unroll
    for (int i = 0; i < 8; i++) {
        int idx = tid + i * 256;                  // 2048 16B chunks per panel
        int row = idx >> 4, ch = idx & 15;
        uint32_t off = (uint32_t)(row * 256 + ((ch ^ (row & 7)) * 16));
        CP_ASYNC16(Abuf + off, Z + (size_t)(r * 128 + row) * 256 + ch * 16);
        CP_ASYNC16(Bbuf + off, Z + (size_t)(c * 128 + row) * 256 + ch * 16);
    }
}

// MMA a 32-col half into acc[32]; optionally drain epi[32] (prev half) into
// rowacc[4] + colacc[8] (4 ex2 per k-step interleaved into the HMMA stream).
template <bool DRAIN>
static __device__ __forceinline__ void mma_half(
    float* __restrict__ acc, float* __restrict__ epi,
    float* __restrict__ rowacc, float* __restrict__ colacc,
    uint32_t buf, int ncol0, int n_loc, int cpar, const uint32_t (*Ar)[8][4])
{
    #pragma unroll
    for (int f = 0; f < 32; f++) acc[f] = 0.f;
    #pragma unroll
    for (int ks = 0; ks < 8; ks++) {
        uint32_t bfr[8];
        #pragma unroll
        for (int pr = 0; pr < 2; pr++) {
            int n = ncol0 + pr * 16 + n_loc;
            uint32_t addr = buf + (uint32_t)n * 256u
                          + (uint32_t)(((2 * ks + cpar) ^ (n_loc & 7)) * 16);
            ldm_x4(bfr[pr*4+0], bfr[pr*4+1], bfr[pr*4+2], bfr[pr*4+3], addr);
        }
        #pragma unroll
        for (int mi = 0; mi < 2; mi++) {
            mma16816(&acc[mi*16 + 0],  Ar[mi][ks], &bfr[0]);
            mma16816(&acc[mi*16 + 4],  Ar[mi][ks], &bfr[2]);
            mma16816(&acc[mi*16 + 8],  Ar[mi][ks], &bfr[4]);
            mma16816(&acc[mi*16 + 12], Ar[mi][ks], &bfr[6]);
        }
        if (DRAIN) {
            #pragma unroll
            for (int u = 0; u < 4; u++) {
                int f = ks * 4 + u;
                float e = ex2f(fmaf(epi[f], C1, -C1));
                rowacc[((f >> 4) << 1) | ((f & 3) >> 1)] += e;
                colacc[(((f >> 2) & 3) << 1) | (f & 1)] += e;
            }
        }
    }
}

// plain drain of epi[32]
static __device__ __forceinline__ void drain32(
    const float* __restrict__ epi, float* __restrict__ rowacc,
    float* __restrict__ colacc)
{
    #pragma unroll
    for (int f = 0; f < 32; f++) {
        float e = ex2f(fmaf(epi[f], C1, -C1));
        rowacc[((f >> 4) << 1) | ((f & 3) >> 1)] += e;
        colacc[(((f >> 2) & 3) << 1) | (f & 1)] += e;
    }
}

// column flush: reduce across the 8 row-lane-groups, lanes 0-3 atomicAdd
static __device__ __forceinline__ void colflush(float* __restrict__ colacc,
                                                int colbase, int lane) {
    #pragma unroll
    for (int q = 0; q < 8; q++) {
        colacc[q] += __shfl_xor_sync(0xffffffffu, colacc[q], 4);
        colacc[q] += __shfl_xor_sync(0xffffffffu, colacc[q], 8);
        colacc[q] += __shfl_xor_sync(0xffffffffu, colacc[q], 16);
    }
    if (lane < 4) {
        #pragma unroll
        for (int q = 0; q < 8; q++) {
            int col = colbase + (q >> 1) * 8 + 2 * lane + (q & 1);
            atomicAdd(&g_rowsum[col], colacc[q]);
        }
    }
}

// ---------- kernels ----------
__global__ void norm_kernel(const float* __restrict__ zi,
                            const float* __restrict__ zj) {
    int gt = blockIdx.x * blockDim.x + threadIdx.x;
    if (gt < NN) g_rowsum[gt] = 0.f;
    if (gt == 0) { g_loss = 0.f; g_done = 0u; }
    int row = gt >> 5;
    int lane = threadIdx.x & 31;
    if (row >= NN) return;
    const float* src = (row < NB) ? (zi + (size_t)row * 128)
                                  : (zj + (size_t)(row - NB) * 128);
    float4 v = ((const float4*)src)[lane];
    float ss = v.x*v.x + v.y*v.y + v.z*v.z + v.w*v.w;
    #pragma unroll
    for (int o = 16; o; o >>= 1) ss += __shfl_xor_sync(0xffffffffu, ss, o);
    float inv = 1.0f / fmaxf(sqrtf(ss), 1e-12f);
    __nv_bfloat162 p0 = __floats2bfloat162_rn(v.x * inv, v.y * inv);
    __nv_bfloat162 p1 = __floats2bfloat162_rn(v.z * inv, v.w * inv);
    float2 q0 = __bfloat1622float2(p0);
    float2 q1 = __bfloat1622float2(p1);
    float sd = q0.x*q0.x + q0.y*q0.y + q1.x*q1.x + q1.y*q1.y;
    #pragma unroll
    for (int o = 16; o; o >>= 1) sd += __shfl_xor_sync(0xffffffffu, sd, o);
    if (lane == 0) g_self[row] = sd;
    uint2 pk;
    pk.x = *reinterpret_cast<uint32_t*>(&p0);
    pk.y = *reinterpret_cast<uint32_t*>(&p1);
    *reinterpret_cast<uint2*>(g_Zb + (size_t)row * 256 + lane * 8) = pk;
}

__global__ void __launch_bounds__(256, 1) sim_kernel() {
    extern __shared__ unsigned char smraw[];
    uint32_t s0 = smem_u32(smraw);
    uint32_t Ab[2] = { s0, s0 + 32768u };
    uint32_t Bb[2] = { s0 + 65536u, s0 + 98304u };

    int tid = threadIdx.x, lane = tid & 31, w = tid >> 5;
    int wm = w & 3, wn = w >> 2;

    // prologue: stage tiles k0, k0+GRID
    int k0 = blockIdx.x;
    #pragma unroll
    for (int p = 0; p < 2; p++) {
        int k = k0 + p * GRID;
        if (k < NT) { int r, c; decode(k, r, c); stage(Ab[p], Bb[p], r, c, tid); }
        CP_COMMIT();
    }

    int n_loc = (lane & 7) + ((lane >> 4) << 3);
    int cpar = (lane >> 3) & 1;
    int row_loc = (lane & 7) + ((lane >> 3) & 1) * 8;
    int kpar = (lane >> 4) & 1;

    float rowacc[4], colacc[8];
    float accA[32], accB[32];

    int t = 0;
    for (int k = k0; k < NT; k += GRID, t++) {
        int buf = t & 1;
        CP_WAIT(1);
        __syncthreads();
        int r, c;
        decode(k, r, c);

        // A fragments for this tile
        uint32_t Ar[2][8][4];
        uint32_t abase = Ab[buf] + (uint32_t)(wm * 32 + row_loc) * 256u;
        #pragma unroll
        for (int ma = 0; ma < 2; ma++)
            #pragma unroll
            for (int ks = 0; ks < 8; ks++) {
                uint32_t addr = abase + (uint32_t)(ma * 16) * 256u
                              + (uint32_t)(((2 * ks + kpar) ^ (row_loc & 7)) * 16);
                ldm_x4(Ar[ma][ks][0], Ar[ma][ks][1], Ar[ma][ks][2], Ar[ma][ks][3], addr);
            }

        #pragma unroll
        for (int q = 0; q < 4; q++) rowacc[q] = 0.f;
        #pragma unroll
        for (int q = 0; q < 8; q++) colacc[q] = 0.f;

        int nbase = wn * 64;
        mma_half<false>(accA, accA, rowacc, colacc, Bb[buf], nbase, n_loc, cpar, Ar);
        mma_half<true >(accB, accA, rowacc, colacc, Bb[buf], nbase + 32, n_loc, cpar, Ar);
        if (r != c) colflush(colacc, c * 128 + nbase, lane);       // half0 cols
        #pragma unroll
        for (int q = 0; q < 8; q++) colacc[q] = 0.f;
        drain32(accB, rowacc, colacc);
        if (r != c) colflush(colacc, c * 128 + nbase + 32, lane);  // half1 cols

        // row flush
        #pragma unroll
        for (int q = 0; q < 4; q++) {
            rowacc[q] += __shfl_xor_sync(0xffffffffu, rowacc[q], 1);
            rowacc[q] += __shfl_xor_sync(0xffffffffu, rowacc[q], 2);
        }
        if ((lane & 3) == 0) {
            int rbase = r * 128 + wm * 32 + (lane >> 2);
            atomicAdd(&g_rowsum[rbase],      rowacc[0]);
            atomicAdd(&g_rowsum[rbase + 8],  rowacc[1]);
            atomicAdd(&g_rowsum[rbase + 16], rowacc[2]);
            atomicAdd(&g_rowsum[rbase + 24], rowacc[3]);
        }

        __syncthreads();                    // all warps done with buf
        int k2 = k + 2 * GRID;
        if (k2 < NT) { int r2, c2; decode(k2, r2, c2); stage(Ab[buf], Bb[buf], r2, c2, tid); }
        CP_COMMIT();
    }
}

// one warp per POSITIVE PAIR (p, p+NB): pos dot once, both rows' losses
__global__ void finish_kernel(float* __restrict__ out) {
    __shared__ float sh[8];
    int tid = threadIdx.x, lane = tid & 31, w = tid >> 5;
    int p = blockIdx.x * 8 + w;                   // 0..4095
    int q = p + NB;
    uint2 ua = *reinterpret_cast<const uint2*>(g_Zb + (size_t)p * 256 + lane * 8);
    uint2 ub = *reinterpret_cast<const uint2*>(g_Zb + (size_t)q * 256 + lane * 8);
    float2 a0 = __bfloat1622float2(*reinterpret_cast<__nv_bfloat162*>(&ua.x));
    float2 a1 = __bfloat1622float2(*reinterpret_cast<__nv_bfloat162*>(&ua.y));
    float2 b0 = __bfloat1622float2(*reinterpret_cast<__nv_bfloat162*>(&ub.x));
    float2 b1 = __bfloat1622float2(*reinterpret_cast<__nv_bfloat162*>(&ub.y));
    float pd = a0.x*b0.x + a0.y*b0.y + a1.x*b1.x + a1.y*b1.y;
    #pragma unroll
    for (int o = 16; o; o >>= 1) pd += __shfl_xor_sync(0xffffffffu, pd, o);
    if (lane == 0) {
        float self_p = ex2f(fmaf(g_self[p], C1, -C1));
        float self_q = ex2f(fmaf(g_self[q], C1, -C1));
        sh[w] = 4.0f + logf(g_rowsum[p] - self_p) + logf(g_rowsum[q] - self_q)
              - 4.0f * pd;                        // both rows share s_pos = 2*pd
    }
    __syncthreads();
    if (tid == 0) {
        float t = 0.f;
        #pragma unroll
        for (int kk = 0; kk < 8; kk++) t += sh[kk];
        atomicAdd(&g_loss, t);
        __threadfence();
        unsigned int done = atomicAdd(&g_done, 1u);
        if (done == (unsigned int)(gridDim.x - 1)) {
            out[0] = g_loss * (1.0f / (float)NN);
        }
    }
}

extern "C" void kernel_launch(void* const* d_in, const int* in_sizes, int n_in,
                              void* d_out, int out_size) {
    const float* zi = (const float*)d_in[0];
    const float* zj = (const float*)d_in[1];
    float* out = (float*)d_out;
    (void)in_sizes; (void)n_in; (void)out_size;

    (void)cudaFuncSetAttribute(sim_kernel,
                               cudaFuncAttributeMaxDynamicSharedMemorySize,
                               131072);

    norm_kernel<<<1024, 256>>>(zi, zj);
    sim_kernel<<<GRID, 256, 131072>>>();
    finish_kernel<<<NB / 8, 256>>>(out);
}

// round 14
// speedup vs baseline: 1.5356x; 1.2144x over previous
#include <cuda_runtime.h>
#include <cuda_bf16.h>
#include <cstdint>
#include <math.h>

// NT-Xent loss, B=4096, D=128, N=8192, T=0.5 — mma.sync bf16, SYMMETRIC v2
// R14: serpentine strip-contiguous tile chunks (130 blocks x 16 tiles), A
// staged/ldmatrix'd only on strip change (double-buffered), B-only per-tile
// staging, and exp affine folded into the stored data (term = ex2(dot')).

#define NB   4096
#define NN   8192
#define NT   2080
#define TPB  16              // tiles per block
#define NBLK 130
#define C1   2.8853900817779268f   // 2*log2(e)
#define SC   1.69864364f           // sqrt(C1); rows stored scaled by SC
#define LN2  0.69314718055994531f  // 2/C1

__device__ __align__(16) unsigned char g_Zb[NN * 256];  // bf16 rows (scaled)
__device__ float g_rowsum[NN];
__device__ float g_self[NN];     // scaled self-dot (dot' of row with itself)
__device__ float g_loss;
__device__ unsigned int g_done;

// ---------- helpers ----------
static __device__ __forceinline__ uint32_t smem_u32(const void* p) {
    uint32_t a;
    asm("{ .reg .u64 t; cvta.to.shared.u64 t, %1; cvt.u32.u64 %0, t; }"
        : "=r"(a) : "l"(p));
    return a;
}
#define CP_ASYNC16(dst, src) \
    asm volatile("cp.async.cg.shared.global [%0], [%1], 16;" :: "r"(dst), "l"(src))
#define CP_COMMIT() asm volatile("cp.async.commit_group;")
#define CP_WAIT(n)  asm volatile("cp.async.wait_group %0;" :: "n"(n))

static __device__ __forceinline__ void ldm_x4(uint32_t& r0, uint32_t& r1,
                                              uint32_t& r2, uint32_t& r3,
                                              uint32_t addr) {
    asm volatile("ldmatrix.sync.aligned.m8n8.x4.shared.b16 {%0,%1,%2,%3}, [%4];"
                 : "=r"(r0), "=r"(r1), "=r"(r2), "=r"(r3) : "r"(addr));
}
static __device__ __forceinline__ void mma16816(float* c, const uint32_t* a,
                                                const uint32_t* b) {
    asm volatile(
        "mma.sync.aligned.m16n8k16.row.col.f32.bf16.bf16.f32 "
        "{%0,%1,%2,%3}, {%4,%5,%6,%7}, {%8,%9}, {%0,%1,%2,%3};"
        : "+f"(c[0]), "+f"(c[1]), "+f"(c[2]), "+f"(c[3])
        : "r"(a[0]), "r"(a[1]), "r"(a[2]), "r"(a[3]), "r"(b[0]), "r"(b[1]));
}
static __device__ __forceinline__ float ex2f(float x) {
    float r;
    asm("ex2.approx.f32 %0, %1;" : "=f"(r) : "f"(x));
    return r;
}

// serpentine strip order: pairs (r=p len 64-p, r=63-p len p+1), 65 tiles/pair
static __device__ __forceinline__ void decode(int q, int& r, int& c) {
    int p = q / 65;
    int off = q - p * 65;
    int len1 = 64 - p;
    if (off < len1) { r = p; c = p + off; }
    else            { r = 63 - p; c = r + (off - len1); }
}

// stage one 128-row panel (32KB): 8 cp.async/thread
static __device__ __forceinline__ void stageP(uint32_t dst, int panel, int tid) {
    const unsigned char* Z = g_Zb;
    #pragma unroll
    for (int i = 0; i < 8; i++) {
        int idx = tid + i * 256;
        int row = idx >> 4, ch = idx & 15;
        uint32_t off = (uint32_t)(row * 256 + ((ch ^ (row & 7)) * 16));
        CP_ASYNC16(dst + off, Z + (size_t)(panel * 128 + row) * 256 + ch * 16);
    }
}

// MMA 32-col half into acc[32]; optionally drain epi[32] (prev half):
// term = ex2(dot'), accumulated into rowacc[4] and colacc[8].
template <bool DRAIN>
static __device__ __forceinline__ void mma_half(
    float* __restrict__ acc, float* __restrict__ epi,
    float* __restrict__ rowacc, float* __restrict__ colacc,
    uint32_t buf, int ncol0, int n_loc, int cpar, const uint32_t (*Ar)[8][4])
{
    #pragma unroll
    for (int f = 0; f < 32; f++) acc[f] = 0.f;
    #pragma unroll
    for (int ks = 0; ks < 8; ks++) {
        uint32_t bfr[8];
        #pragma unroll
        for (int pr = 0; pr < 2; pr++) {
            int n = ncol0 + pr * 16 + n_loc;
            uint32_t addr = buf + (uint32_t)n * 256u
                          + (uint32_t)(((2 * ks + cpar) ^ (n_loc & 7)) * 16);
            ldm_x4(bfr[pr*4+0], bfr[pr*4+1], bfr[pr*4+2], bfr[pr*4+3], addr);
        }
        #pragma unroll
        for (int mi = 0; mi < 2; mi++) {
            mma16816(&acc[mi*16 + 0],  Ar[mi][ks], &bfr[0]);
            mma16816(&acc[mi*16 + 4],  Ar[mi][ks], &bfr[2]);
            mma16816(&acc[mi*16 + 8],  Ar[mi][ks], &bfr[4]);
            mma16816(&acc[mi*16 + 12], Ar[mi][ks], &bfr[6]);
        }
        if (DRAIN) {
            #pragma unroll
            for (int u = 0; u < 4; u++) {
                int f = ks * 4 + u;
                float e = ex2f(epi[f]);
                rowacc[((f >> 4) << 1) | ((f & 3) >> 1)] += e;
                colacc[(((f >> 2) & 3) << 1) | (f & 1)] += e;
            }
        }
    }
}

static __device__ __forceinline__ void drain32(
    const float* __restrict__ epi, float* __restrict__ rowacc,
    float* __restrict__ colacc)
{
    #pragma unroll
    for (int f = 0; f < 32; f++) {
        float e = ex2f(epi[f]);
        rowacc[((f >> 4) << 1) | ((f & 3) >> 1)] += e;
        colacc[(((f >> 2) & 3) << 1) | (f & 1)] += e;
    }
}

static __device__ __forceinline__ void colflush(float* __restrict__ colacc,
                                                int colbase, int lane) {
    #pragma unroll
    for (int q = 0; q < 8; q++) {
        colacc[q] += __shfl_xor_sync(0xffffffffu, colacc[q], 4);
        colacc[q] += __shfl_xor_sync(0xffffffffu, colacc[q], 8);
        colacc[q] += __shfl_xor_sync(0xffffffffu, colacc[q], 16);
    }
    if (lane < 4) {
        #pragma unroll
        for (int q = 0; q < 8; q++) {
            int col = colbase + (q >> 1) * 8 + 2 * lane + (q & 1);
            atomicAdd(&g_rowsum[col], colacc[q]);
        }
    }
}

// ---------- kernels ----------
__global__ void norm_kernel(const float* __restrict__ zi,
                            const float* __restrict__ zj) {
    int gt = blockIdx.x * blockDim.x + threadIdx.x;
    if (gt < NN) g_rowsum[gt] = 0.f;
    if (gt == 0) { g_loss = 0.f; g_done = 0u; }
    int row = gt >> 5;
    int lane = threadIdx.x & 31;
    if (row >= NN) return;
    const float* src = (row < NB) ? (zi + (size_t)row * 128)
                                  : (zj + (size_t)(row - NB) * 128);
    float4 v = ((const float4*)src)[lane];
    float ss = v.x*v.x + v.y*v.y + v.z*v.z + v.w*v.w;
    #pragma unroll
    for (int o = 16; o; o >>= 1) ss += __shfl_xor_sync(0xffffffffu, ss, o);
    float sca = SC / fmaxf(sqrtf(ss), 1e-12f);     // normalize AND scale by SC
    __nv_bfloat162 p0 = __floats2bfloat162_rn(v.x * sca, v.y * sca);
    __nv_bfloat162 p1 = __floats2bfloat162_rn(v.z * sca, v.w * sca);
    float2 q0 = __bfloat1622float2(p0);
    float2 q1 = __bfloat1622float2(p1);
    float sd = q0.x*q0.x + q0.y*q0.y + q1.x*q1.x + q1.y*q1.y;   // scaled self
    #pragma unroll
    for (int o = 16; o; o >>= 1) sd += __shfl_xor_sync(0xffffffffu, sd, o);
    if (lane == 0) g_self[row] = sd;
    uint2 pk;
    pk.x = *reinterpret_cast<uint32_t*>(&p0);
    pk.y = *reinterpret_cast<uint32_t*>(&p1);
    *reinterpret_cast<uint2*>(g_Zb + (size_t)row * 256 + lane * 8) = pk;
}

__global__ void __launch_bounds__(256, 1) sim_kernel() {
    extern __shared__ unsigned char smraw[];
    uint32_t s0 = smem_u32(smraw);
    uint32_t Abuf[2] = { s0, s0 + 32768u };
    uint32_t Bbuf[2] = { s0 + 65536u, s0 + 98304u };

    int tid = threadIdx.x, lane = tid & 31, w = tid >> 5;
    int wm = w & 3, wn = w >> 2;
    int q0 = blockIdx.x * TPB;

    int n_loc = (lane & 7) + ((lane >> 4) << 3);
    int cpar = (lane >> 3) & 1;
    int row_loc = (lane & 7) + ((lane >> 3) & 1) * 8;
    int kpar = (lane >> 4) & 1;

    // prologue
    int r0p, c0p, r1p, c1p;
    decode(q0, r0p, c0p);
    decode(q0 + 1, r1p, c1p);
    stageP(Abuf[0], r0p, tid);
    stageP(Bbuf[0], c0p, tid);
    CP_COMMIT();
    int stgA = 1;
    if (r1p != r0p) { stageP(Abuf[1], r1p, tid); stgA = 0; }
    stageP(Bbuf[1], c1p, tid);
    CP_COMMIT();

    uint32_t Ar[2][8][4];
    float rowacc[4], colacc[8];
    float accA[32], accB[32];
    int useA = 0, rprev = -1;

    for (int t = 0; t < TPB; t++) {
        int q = q0 + t;
        int r, c;
        decode(q, r, c);
        int buf = t & 1;

        CP_WAIT(1);
        __syncthreads();

        if (r != rprev) {
            if (t > 0) useA ^= 1;
            uint32_t abase = Abuf[useA] + (uint32_t)(wm * 32 + row_loc) * 256u;
            #pragma unroll
            for (int ma = 0; ma < 2; ma++)
                #pragma unroll
                for (int ks = 0; ks < 8; ks++) {
                    uint32_t addr = abase + (uint32_t)(ma * 16) * 256u
                                  + (uint32_t)(((2 * ks + kpar) ^ (row_loc & 7)) * 16);
                    ldm_x4(Ar[ma][ks][0], Ar[ma][ks][1], Ar[ma][ks][2], Ar[ma][ks][3], addr);
                }
        }
        rprev = r;

        #pragma unroll
        for (int k2 = 0; k2 < 4; k2++) rowacc[k2] = 0.f;
        #pragma unroll
        for (int k2 = 0; k2 < 8; k2++) colacc[k2] = 0.f;

        int nbase = wn * 64;
        mma_half<false>(accA, accA, rowacc, colacc, Bbuf[buf], nbase, n_loc, cpar, Ar);
        mma_half<true >(accB, accA, rowacc, colacc, Bbuf[buf], nbase + 32, n_loc, cpar, Ar);
        if (r != c) colflush(colacc, c * 128 + nbase, lane);
        #pragma unroll
        for (int k2 = 0; k2 < 8; k2++) colacc[k2] = 0.f;
        drain32(accB, rowacc, colacc);
        if (r != c) colflush(colacc, c * 128 + nbase + 32, lane);

        #pragma unroll
        for (int k2 = 0; k2 < 4; k2++) {
            rowacc[k2] += __shfl_xor_sync(0xffffffffu, rowacc[k2], 1);
            rowacc[k2] += __shfl_xor_sync(0xffffffffu, rowacc[k2], 2);
        }
        if ((lane & 3) == 0) {
            int rbase = r * 128 + wm * 32 + (lane >> 2);
            atomicAdd(&g_rowsum[rbase],      rowacc[0]);
            atomicAdd(&g_rowsum[rbase + 8],  rowacc[1]);
            atomicAdd(&g_rowsum[rbase + 16], rowacc[2]);
            atomicAdd(&g_rowsum[rbase + 24], rowacc[3]);
        }

        __syncthreads();                          // all warps done with Bbuf[buf]

        int q2 = q + 2;
        if (t + 2 < TPB) {
            int r2, c2, rn, cn;
            decode(q2, r2, c2);
            decode(q + 1, rn, cn);
            stageP(Bbuf[buf], c2, tid);
            if (r2 != rn) { stageP(Abuf[stgA], r2, tid); stgA ^= 1; }
        }
        CP_COMMIT();
    }
}

// one warp per positive pair (p, p+NB)
__global__ void finish_kernel(float* __restrict__ out) {
    __shared__ float sh[8];
    int tid = threadIdx.x, lane = tid & 31, w = tid >> 5;
    int p = blockIdx.x * 8 + w;
    int q = p + NB;
    uint2 ua = *reinterpret_cast<const uint2*>(g_Zb + (size_t)p * 256 + lane * 8);
    uint2 ub = *reinterpret_cast<const uint2*>(g_Zb + (size_t)q * 256 + lane * 8);
    float2 a0 = __bfloat1622float2(*reinterpret_cast<__nv_bfloat162*>(&ua.x));
    float2 a1 = __bfloat1622float2(*reinterpret_cast<__nv_bfloat162*>(&ua.y));
    float2 b0 = __bfloat1622float2(*reinterpret_cast<__nv_bfloat162*>(&ub.x));
    float2 b1 = __bfloat1622float2(*reinterpret_cast<__nv_bfloat162*>(&ub.y));
    float pd = a0.x*b0.x + a0.y*b0.y + a1.x*b1.x + a1.y*b1.y;   // scaled dot'
    #pragma unroll
    for (int o = 16; o; o >>= 1) pd += __shfl_xor_sync(0xffffffffu, pd, o);
    if (lane == 0) {
        // loss_i = 2 + ln(2^{-C1}(rowsum - self)) - s_pos
        //        = ln(rowsum - self) - ln2*dot'_pos   (2 - C1*ln2 = 0)
        float rsp = g_rowsum[p] - ex2f(g_self[p]);
        float rsq = g_rowsum[q] - ex2f(g_self[q]);
        sh[w] = logf(rsp) + logf(rsq) - 2.0f * LN2 * pd;
    }
    __syncthreads();
    if (tid == 0) {
        float t = 0.f;
        #pragma unroll
        for (int kk = 0; kk < 8; kk++) t += sh[kk];
        atomicAdd(&g_loss, t);
        __threadfence();
        unsigned int done = atomicAdd(&g_done, 1u);
        if (done == (unsigned int)(gridDim.x - 1)) {
            out[0] = g_loss * (1.0f / (float)NN);
        }
    }
}

extern "C" void kernel_launch(void* const* d_in, const int* in_sizes, int n_in,
                              void* d_out, int out_size) {
    const float* zi = (const float*)d_in[0];
    const float* zj = (const float*)d_in[1];
    float* out = (float*)d_out;
    (void)in_sizes; (void)n_in; (void)out_size;

    (void)cudaFuncSetAttribute(sim_kernel,
                               cudaFuncAttributeMaxDynamicSharedMemorySize,
                               131072);

    norm_kernel<<<1024, 256>>>(zi, zj);
    sim_kernel<<<NBLK, 256, 131072>>>();
    finish_kernel<<<NB / 8, 256>>>(out);
}